// round 14
// baseline (speedup 1.0000x reference)
#include <cuda_runtime.h>
#include <cuda_fp16.h>
#include <cstdint>
#include <math.h>

#define BB   16
#define CC   256
#define HWN  4096
#define KK   4
#define HIDN 512
#define EPS_W 1e-8f
#define LN_EPS 1e-5f
#define SCALE 0.0625f   // C^-0.5 = 1/16
#define NBLK 256
#define NGRP 16
#define GBLK 16

// ---------------- scratch (static device globals; no allocation) ----------------
static __device__ __align__(16) __half g_xnl [BB*HWN*CC];  // LN'd input (b,n,c) fp16
static __device__ __align__(16) float g_slots[BB*KK*CC];
static __device__ __align__(16) float g_qt  [BB*KK*CC];
static __device__            float g_qb  [BB*KK];
static __device__ __align__(16) float g_A   [BB*KK*CC];
static __device__            float g_S   [BB*KK];
static __device__ __align__(16) float g_spre[BB*KK*CC];
static __device__ __align__(16) float g_h   [BB*KK*HIDN];
static __device__ __align__(16) float g_Wvu [CC*CC];   // (Wu2@Wv)[d][c]
static __device__            float g_bvu [CC];
static __device__ __align__(16) float g_Wqk [CC*CC];   // scale*(Wk^T Wq)[c_out][e]
static __device__            float g_qtb [CC];
static __device__ __align__(16) float g_wqbk[CC];
static __device__            float g_bqbk;

// global barrier (phase 0 only)
static __device__ unsigned int g_bar_count = 0;
static __device__ volatile unsigned int g_bar_gen = 0;
// per-group barriers, 64B apart
static __device__ unsigned int g_gcount[NGRP * 16];
static __device__ volatile unsigned int g_ggen[NGRP * 16];

// dynamic smem layout for attn phase (bytes); tile = 128 tokens, x stride 133
#define SX_WORDS   (128 * 133)
#define OFF_SX     0
#define OFF_QT     (SX_WORDS * 4)
#define OFF_PART   (OFF_QT + 4 * 128 * 8)
#define OFF_SA     (OFF_PART + 256 * 16)
#define OFF_QB     (OFF_SA + 128 * 16)
#define OFF_SRED   (OFF_QB + 16)
#define SMEM_ATTN  (OFF_SRED + 16 * 4 + 16)

// update-phase view
#define U_OFF_IN    0
#define U_OFF_IN2   8192
#define U_OFF_SLAB  12288
#define U_OFF_RED   49152

__device__ __forceinline__ float gelu_f(float x) {
    return 0.5f * x * (1.0f + erff(x * 0.70710678118654752f));
}

__device__ __forceinline__ void grid_bar() {
    __syncthreads();
    if (threadIdx.x == 0) {
        __threadfence();
        unsigned int gen = g_bar_gen;
        if (atomicAdd(&g_bar_count, 1u) == NBLK - 1) {
            atomicExch(&g_bar_count, 0u);
            __threadfence();
            g_bar_gen = gen + 1;
        } else {
            while (g_bar_gen == gen) { __nanosleep(64); }
        }
        __threadfence();
    }
    __syncthreads();
}

__device__ __forceinline__ void group_bar(int g) {
    __syncthreads();
    if (threadIdx.x == 0) {
        __threadfence();
        unsigned int gen = g_ggen[g * 16];
        if (atomicAdd(&g_gcount[g * 16], 1u) == GBLK - 1) {
            atomicExch(&g_gcount[g * 16], 0u);
            __threadfence();
            g_ggen[g * 16] = gen + 1;
        } else {
            while (g_ggen[g * 16] == gen) { __nanosleep(32); }
        }
        __threadfence();
    }
    __syncthreads();
}

// LN of 4 rows (stride 256) in smem `sin`, in place; red = 256-float scratch.
__device__ __forceinline__ void ln_apply4(float* sin, float* red,
                                          const float* __restrict__ gg,
                                          const float* __restrict__ bb, int tid) {
    int r = tid >> 6, t = tid & 63;
    float4 v = ((const float4*)(sin + r * 256))[t];
    float s = v.x + v.y + v.z + v.w;
    float q = v.x * v.x + v.y * v.y + v.z * v.z + v.w * v.w;
    #pragma unroll
    for (int off = 16; off; off >>= 1) {
        s += __shfl_xor_sync(0xffffffffu, s, off);
        q += __shfl_xor_sync(0xffffffffu, q, off);
    }
    int w = tid >> 5;
    if ((tid & 31) == 0) { red[w * 2] = s; red[w * 2 + 1] = q; }
    __syncthreads();
    if (tid < 4) {
        float S = red[tid * 4] + red[tid * 4 + 2];
        float Q = red[tid * 4 + 1] + red[tid * 4 + 3];
        float m = S * (1.0f / 256.0f);
        red[16 + tid * 2] = m;
        red[17 + tid * 2] = rsqrtf(Q * (1.0f / 256.0f) - m * m + LN_EPS);
    }
    __syncthreads();
    #pragma unroll
    for (int i = 0; i < 4; i++) {
        int idx = i * 256 + tid; int rr = idx >> 8, c = idx & 255;
        float m = red[16 + rr * 2], rstd = red[17 + rr * 2];
        sin[rr * 256 + c] = (sin[rr * 256 + c] - m) * rstd * gg[c] + bb[c];
    }
    __syncthreads();
}

// ---------------- phase-0 device fns ----------------
__device__ void prep_unit(int bid, char* smraw, int tid,
                          const float* __restrict__ Wq, const float* __restrict__ Wk,
                          const float* __restrict__ bq, const float* __restrict__ Wv,
                          const float* __restrict__ bv, const float* __restrict__ Wu) {
    float* sbuf = (float*)smraw;               // 32*260
    float* wcs  = sbuf + 32 * 260;             // 1024 floats
    if (bid < 64) {
        int d0 = bid * 4;
        for (int idx = tid; idx < CC * 4; idx += 256) {
            int dl = idx & 3, e = idx >> 2;
            wcs[e * 4 + dl] = Wu[(size_t)(d0 + dl) * 512 + 256 + e];
        }
        __syncthreads();
        float a0 = 0.f, a1 = 0.f, a2 = 0.f, a3 = 0.f;
        for (int ch = 0; ch < 8; ch++) {
            #pragma unroll 8
            for (int it = 0; it < 32; it++)
                sbuf[it * 260 + tid] = Wv[(size_t)(ch * 32 + it) * CC + tid];
            __syncthreads();
            #pragma unroll 8
            for (int el = 0; el < 32; el++) {
                float x = sbuf[el * 260 + tid];
                float4 w = *(const float4*)&wcs[(ch * 32 + el) * 4];
                a0 += w.x * x; a1 += w.y * x; a2 += w.z * x; a3 += w.w * x;
            }
            __syncthreads();
        }
        g_Wvu[(size_t)(d0 + 0) * CC + tid] = a0;
        g_Wvu[(size_t)(d0 + 1) * CC + tid] = a1;
        g_Wvu[(size_t)(d0 + 2) * CC + tid] = a2;
        g_Wvu[(size_t)(d0 + 3) * CC + tid] = a3;
        if (tid < 4) {
            float s = 0.f;
            for (int e = 0; e < CC; e++)
                s += Wu[(size_t)(d0 + tid) * 512 + 256 + e] * bv[e];
            g_bvu[d0 + tid] = s;
        }
    } else {
        int c0 = (bid - 64) * 4;
        float a0 = 0.f, a1 = 0.f, a2 = 0.f, a3 = 0.f;
        for (int ch = 0; ch < 8; ch++) {
            #pragma unroll 8
            for (int it = 0; it < 32; it++)
                sbuf[it * 260 + tid] = Wq[(size_t)(ch * 32 + it) * CC + tid];
            if (tid < 128) {
                int dl = tid >> 2, cl = tid & 3;
                wcs[dl * 4 + cl] = Wk[(size_t)(ch * 32 + dl) * CC + c0 + cl];
            }
            __syncthreads();
            #pragma unroll 8
            for (int dl = 0; dl < 32; dl++) {
                float x = sbuf[dl * 260 + tid];
                a0 += wcs[dl * 4 + 0] * x; a1 += wcs[dl * 4 + 1] * x;
                a2 += wcs[dl * 4 + 2] * x; a3 += wcs[dl * 4 + 3] * x;
            }
            __syncthreads();
        }
        g_Wqk[(size_t)(c0 + 0) * CC + tid] = SCALE * a0;
        g_Wqk[(size_t)(c0 + 1) * CC + tid] = SCALE * a1;
        g_Wqk[(size_t)(c0 + 2) * CC + tid] = SCALE * a2;
        g_Wqk[(size_t)(c0 + 3) * CC + tid] = SCALE * a3;
        if (tid < 4) {
            float s = 0.f;
            for (int d = 0; d < CC; d++) s += Wk[(size_t)d * CC + c0 + tid] * bq[d];
            g_qtb[c0 + tid] = SCALE * s;
        }
    }
    __syncthreads();
}

__device__ void prep_bias(char* smraw, int tid,
                          const float* __restrict__ Wq, const float* __restrict__ bq,
                          const float* __restrict__ bk) {
    float* sbuf = (float*)smraw;
    float s = 0.f;
    #pragma unroll 8
    for (int d = 0; d < CC; d++) s += Wq[(size_t)d * CC + tid] * bk[d];
    g_wqbk[tid] = SCALE * s;
    sbuf[tid] = bq[tid] * bk[tid];
    __syncthreads();
    #pragma unroll
    for (int st = 128; st > 0; st >>= 1) {
        if (tid < st) sbuf[tid] += sbuf[tid + st];
        __syncthreads();
    }
    if (tid == 0) g_bqbk = SCALE * sbuf[0];
    __syncthreads();
}

// one LN-input tile (32 tokens): t in [0,2048)
__device__ void ln_tile(int t, char* smraw, int tid,
                        const float* __restrict__ x,
                        const float* __restrict__ lg,
                        const float* __restrict__ lb) {
    float* sm = (float*)smraw;        // 256*33
    float* ps = sm + 256 * 33;
    float* pq = ps + 256;
    float* mu = pq + 256;
    float* rs = mu + 32;
    int b = t >> 7;
    int tile = t & 127;
    int n0 = tile * 32;
    __syncthreads();

    const float* xb = x + ((size_t)b * CC) * HWN + n0;
    #pragma unroll 8
    for (int it = 0; it < 32; it++) {
        int idx = it * 256 + tid;
        int n = idx & 31, c = idx >> 5;
        sm[c * 33 + n] = xb[(size_t)c * HWN + n];
    }
    __syncthreads();

    int p = tid >> 5, tn = tid & 31;
    float s = 0.f, sq = 0.f;
    #pragma unroll 8
    for (int cc = 0; cc < 32; cc++) {
        float v = sm[(p * 32 + cc) * 33 + tn];
        s += v; sq += v * v;
    }
    ps[p * 32 + tn] = s; pq[p * 32 + tn] = sq;
    __syncthreads();
    if (tid < 32) {
        float S = 0.f, Q = 0.f;
        #pragma unroll
        for (int i = 0; i < 8; i++) { S += ps[i * 32 + tid]; Q += pq[i * 32 + tid]; }
        float m = S * (1.0f / 256.0f);
        float var = Q * (1.0f / 256.0f) - m * m;
        mu[tid] = m;
        rs[tid] = rsqrtf(var + LN_EPS);
    }
    __syncthreads();

    float gc = lg[tid], bc = lb[tid];
    __half* out = g_xnl + ((size_t)(b * HWN + n0)) * CC;
    #pragma unroll 8
    for (int it = 0; it < 32; it++) {
        float v = sm[tid * 33 + it];
        out[(size_t)it * CC + tid] = __float2half_rn((v - mu[it]) * rs[it] * gc + bc);
    }
}

// ---------------- attn tile (R9 body, packed qt) ----------------
__device__ __forceinline__ void attn_tile(int t, char* smraw, int tid) {
    unsigned int* sx = (unsigned int*)(smraw + OFF_SX);
    float*  sqtf  = (float*) (smraw + OFF_QT);
    float*  spart = (float*) (smraw + OFF_PART);
    float*  sa    = (float*) (smraw + OFF_SA);
    float*  sqb   = (float*) (smraw + OFF_QB);
    float*  sred  = (float*) (smraw + OFF_SRED);

    int b = t >> 5;
    int tile = t & 31;
    int n0 = tile * 128;

    const uint4* gx = (const uint4*)(g_xnl + ((size_t)(b * HWN + n0)) * CC);
    #pragma unroll
    for (int it = 0; it < 16; it++) {
        int idx = it * 256 + tid;
        int n = idx >> 5, c8 = idx & 31;
        uint4 u = gx[idx];
        unsigned int* dst = sx + n * 133 + c8 * 4;
        dst[0] = u.x; dst[1] = u.y; dst[2] = u.z; dst[3] = u.w;
    }
    #pragma unroll
    for (int it = 0; it < 4; it++) {
        int idx = it * 256 + tid;
        int k = idx & 3, sub = (idx >> 2) & 1, c2 = idx >> 3;
        sqtf[c2 * 8 + sub * 4 + k] = g_qt[(b * KK + k) * CC + c2 * 2 + sub];
    }
    if (tid < 4) sqb[tid] = g_qb[b * KK + tid];
    __syncthreads();

    {
        int n = tid & 127, h = tid >> 7;
        const unsigned int* xrow = sx + n * 133 + h * 64;
        const float4* q4 = (const float4*)sqtf + h * 128;
        float p0 = 0.f, p1 = 0.f, p2 = 0.f, p3 = 0.f;
        #pragma unroll 8
        for (int i = 0; i < 64; i++) {
            __half2 hx = *(const __half2*)&xrow[i];
            float2 xf = __half22float2(hx);
            float4 qa = q4[2 * i];
            float4 qb = q4[2 * i + 1];
            p0 += xf.x * qa.x + xf.y * qb.x;
            p1 += xf.x * qa.y + xf.y * qb.y;
            p2 += xf.x * qa.z + xf.y * qb.z;
            p3 += xf.x * qa.w + xf.y * qb.w;
        }
        ((float4*)spart)[tid] = make_float4(p0, p1, p2, p3);
    }
    __syncthreads();

    if (tid < 128) {
        float4 pa = ((const float4*)spart)[tid];
        float4 pb = ((const float4*)spart)[tid + 128];
        float l0 = pa.x + pb.x + sqb[0];
        float l1 = pa.y + pb.y + sqb[1];
        float l2 = pa.z + pb.z + sqb[2];
        float l3 = pa.w + pb.w + sqb[3];
        float mx = fmaxf(fmaxf(l0, l1), fmaxf(l2, l3));
        float e0 = __expf(l0 - mx), e1 = __expf(l1 - mx);
        float e2 = __expf(l2 - mx), e3 = __expf(l3 - mx);
        float inv = __fdividef(1.0f, e0 + e1 + e2 + e3);
        float a0 = e0 * inv, a1 = e1 * inv, a2 = e2 * inv, a3 = e3 * inv;
        ((float4*)sa)[tid] = make_float4(a0, a1, a2, a3);
        float s0 = a0, s1 = a1, s2 = a2, s3 = a3;
        #pragma unroll
        for (int off = 16; off; off >>= 1) {
            s0 += __shfl_xor_sync(0xffffffffu, s0, off);
            s1 += __shfl_xor_sync(0xffffffffu, s1, off);
            s2 += __shfl_xor_sync(0xffffffffu, s2, off);
            s3 += __shfl_xor_sync(0xffffffffu, s3, off);
        }
        if ((tid & 31) == 0) {
            int w = tid >> 5;
            sred[w * 4 + 0] = s0; sred[w * 4 + 1] = s1;
            sred[w * 4 + 2] = s2; sred[w * 4 + 3] = s3;
        }
    }
    __syncthreads();
    if (tid < 4) {
        float s = sred[tid] + sred[4 + tid] + sred[8 + tid] + sred[12 + tid];
        atomicAdd(&g_S[b * KK + tid], s);
    }

    {
        int w = tid >> 5, L = tid & 31;
        int word = w * 16 + (L & 15);
        bool hi = (L >= 16);
        float2 a0 = {0.f, 0.f}, a1 = {0.f, 0.f}, a2 = {0.f, 0.f}, a3 = {0.f, 0.f};
        #pragma unroll 8
        for (int t2 = 0; t2 < 64; t2++) {
            int nn = hi ? (64 + ((t2 + 16) & 63)) : t2;
            __half2 hx = *(const __half2*)&sx[nn * 133 + word];
            float2 xf = __half22float2(hx);
            float4 av = ((const float4*)sa)[nn];
            a0.x += av.x * xf.x; a0.y += av.x * xf.y;
            a1.x += av.y * xf.x; a1.y += av.y * xf.y;
            a2.x += av.z * xf.x; a2.y += av.z * xf.y;
            a3.x += av.w * xf.x; a3.y += av.w * xf.y;
        }
        a0.x += __shfl_down_sync(0xffffffffu, a0.x, 16);
        a0.y += __shfl_down_sync(0xffffffffu, a0.y, 16);
        a1.x += __shfl_down_sync(0xffffffffu, a1.x, 16);
        a1.y += __shfl_down_sync(0xffffffffu, a1.y, 16);
        a2.x += __shfl_down_sync(0xffffffffu, a2.x, 16);
        a2.y += __shfl_down_sync(0xffffffffu, a2.y, 16);
        a3.x += __shfl_down_sync(0xffffffffu, a3.x, 16);
        a3.y += __shfl_down_sync(0xffffffffu, a3.y, 16);
        if (!hi) {
            int c = 2 * word;
            float* A0 = g_A + (b * KK + 0) * CC + c;
            float* A1 = g_A + (b * KK + 1) * CC + c;
            float* A2 = g_A + (b * KK + 2) * CC + c;
            float* A3 = g_A + (b * KK + 3) * CC + c;
            atomicAdd(A0, a0.x); atomicAdd(A0 + 1, a0.y);
            atomicAdd(A1, a1.x); atomicAdd(A1 + 1, a1.y);
            atomicAdd(A2, a2.x); atomicAdd(A2 + 1, a2.y);
            atomicAdd(A3, a3.x); atomicAdd(A3 + 1, a3.y);
        }
    }
    __syncthreads();
}

// ---------------- qt stage (rg = group, os = in-group block) ----------------
__device__ __forceinline__ void qt_stage(char* smraw, int rg, int os, int tid,
                                         const float* lsg, const float* lsb,
                                         int zeroAS) {
    float* uin  = (float*)(smraw + U_OFF_IN);
    float* slab = (float*)(smraw + U_OFF_SLAB);
    float* red  = (float*)(smraw + U_OFF_RED);

    #pragma unroll
    for (int i = 0; i < 4; i++) {
        int idx = i * 256 + tid; int r = idx >> 8, c = idx & 255;
        uin[r * 256 + c] = g_slots[(rg * 4 + r) * 256 + c];
    }
    #pragma unroll
    for (int i = 0; i < 16; i++) {
        int idx = i * 256 + tid; int j = idx >> 8, c = idx & 255;
        slab[j * 260 + c] = g_Wqk[(size_t)(os * 16 + j) * 256 + c];
    }
    __syncthreads();
    ln_apply4(uin, red, lsg, lsb, tid);

    if (os == 0) {
        int r = tid >> 6, t = tid & 63;
        float4 v = ((const float4*)(uin + r * 256))[t];
        float4 w = ((const float4*)g_wqbk)[t];
        float s = v.x * w.x + v.y * w.y + v.z * w.z + v.w * w.w;
        #pragma unroll
        for (int off = 16; off; off >>= 1) s += __shfl_xor_sync(0xffffffffu, s, off);
        if ((tid & 31) == 0) red[(tid >> 5) * 2] = s;
        __syncthreads();
        if (tid < 4) g_qb[rg * 4 + tid] = red[tid * 4] + red[tid * 4 + 2] + g_bqbk;
    }

    int r = tid >> 6, j = (tid >> 2) & 15, cq = tid & 3;
    float acc = 0.f;
    #pragma unroll 8
    for (int ci = 0; ci < 64; ci++) {
        int c = cq + ci * 4;
        acc += uin[r * 256 + c] * slab[j * 260 + c];
    }
    acc += __shfl_xor_sync(0xffffffffu, acc, 1);
    acc += __shfl_xor_sync(0xffffffffu, acc, 2);
    if (cq == 0) {
        int cc = os * 16 + j, row = rg * 4 + r;
        g_qt[row * 256 + cc] = acc + g_qtb[cc];
    }
    if (zeroAS) {
        if (tid < 64) {
            int r2 = tid >> 4, j2 = tid & 15;
            g_A[(rg * 4 + r2) * 256 + os * 16 + j2] = 0.f;
        }
        if (os == 0 && tid < 4) g_S[rg * 4 + tid] = 0.f;
    }
}

// ---------------- THE kernel ----------------
__global__ void __launch_bounds__(256, 2) k_mega(
    const float* __restrict__ x,
    const float* __restrict__ lig,  const float* __restrict__ lib,
    const float* __restrict__ smu,  const float* __restrict__ sls,
    const float* __restrict__ noise,
    const float* __restrict__ lsg,  const float* __restrict__ lsb,
    const float* __restrict__ lmg,  const float* __restrict__ lmb,
    const float* __restrict__ Wq,   const float* __restrict__ bq,
    const float* __restrict__ Wk,   const float* __restrict__ bk,
    const float* __restrict__ Wv,   const float* __restrict__ bv,
    const float* __restrict__ Wu,   const float* __restrict__ bu,
    const float* __restrict__ W1,   const float* __restrict__ b1,
    const float* __restrict__ W2,   const float* __restrict__ b2,
    const float* __restrict__ We1,  const float* __restrict__ be1,
    const float* __restrict__ We2,  const float* __restrict__ be2,
    float* __restrict__ out) {
    extern __shared__ __align__(16) char smraw[];
    float* uin  = (float*)(smraw + U_OFF_IN);
    float* uin2 = (float*)(smraw + U_OFF_IN2);
    float* slab = (float*)(smraw + U_OFF_SLAB);
    float* slab2 = slab + 16 * 260;
    float* red  = (float*)(smraw + U_OFF_RED);
    int bid = blockIdx.x;
    int tid = threadIdx.x;
    int g  = bid >> 4;          // group = batch element
    int gb = bid & 15;          // block within group
    int rg = g, os = gb;

    // ================= phase 0 (global) =================
    if (bid < 128) {
        prep_unit(bid, smraw, tid, Wq, Wk, bq, Wv, bv, Wu);
    } else if (bid == 128) {
        prep_bias(smraw, tid, Wq, bq, bk);
    } else if (bid < 193) {
        int row = bid - 129;
        float ns = smu[tid] + expf(sls[tid]) * noise[row * 256 + tid];
        g_slots[row * 256 + tid] = ns;
        g_A[row * 256 + tid] = 0.f;
        if (tid == 0) g_S[row] = 0.f;
    }
    if (bid <= 128) {
        #pragma unroll
        for (int i = 0; i < 4; i++) ln_tile(bid * 4 + i, smraw, tid, x, lig, lib);
    } else {
        for (int t = 516 + (bid - 129); t < 2048; t += 127)
            ln_tile(t, smraw, tid, x, lig, lib);
    }
    grid_bar();

    // ================= per-group pipeline =================
    qt_stage(smraw, rg, os, tid, lsg, lsb, 0);
    group_bar(g);

    for (int it = 0; it < 3; it++) {
        int last = (it == 2);
        // attn: this group's batch only; tiles g*32 + gb*2, +1
        attn_tile(g * 32 + gb * 2, smraw, tid);
        attn_tile(g * 32 + gb * 2 + 1, smraw, tid);
        group_bar(g);

        // ---- S1: spre ----
        {
            #pragma unroll
            for (int i = 0; i < 4; i++) {
                int idx = i * 256 + tid; int r = idx >> 8, c = idx & 255;
                int row = rg * 4 + r;
                uin[r * 256 + c] = g_slots[row * 256 + c];
                float Sv = g_S[row];
                uin2[r * 256 + c] = g_A[row * 256 + c] * (1.0f / (Sv + EPS_W));
            }
            #pragma unroll
            for (int i = 0; i < 16; i++) {
                int idx = i * 256 + tid; int j = idx >> 8, c = idx & 255;
                slab [j * 260 + c] = Wu[(size_t)(os * 16 + j) * 512 + c];
                slab2[j * 260 + c] = g_Wvu[(size_t)(os * 16 + j) * 256 + c];
            }
            __syncthreads();
            int r = tid >> 6, j = (tid >> 2) & 15, cq = tid & 3;
            float acc = 0.f;
            #pragma unroll 8
            for (int ci = 0; ci < 64; ci++) {
                int c = cq + ci * 4;
                acc += uin[r * 256 + c] * slab[j * 260 + c]
                     + uin2[r * 256 + c] * slab2[j * 260 + c];
            }
            acc += __shfl_xor_sync(0xffffffffu, acc, 1);
            acc += __shfl_xor_sync(0xffffffffu, acc, 2);
            if (cq == 0) {
                int d = os * 16 + j, row = rg * 4 + r;
                float Sv = g_S[row];
                float beta = Sv / (Sv + EPS_W);
                g_spre[row * 256 + d] = acc + bu[d] + uin[r * 256 + d]
                                      + beta * g_bvu[d];
            }
        }
        group_bar(g);

        // ---- S2: h = gelu(LN_mlp(spre) @ W1^T + b1) ----
        {
            #pragma unroll
            for (int i = 0; i < 4; i++) {
                int idx = i * 256 + tid; int r = idx >> 8, c = idx & 255;
                uin[r * 256 + c] = g_spre[(rg * 4 + r) * 256 + c];
            }
            #pragma unroll
            for (int i = 0; i < 32; i++) {
                int idx = i * 256 + tid; int j = idx >> 8, c = idx & 255;
                slab[j * 258 + c] = W1[(size_t)(os * 32 + j) * 256 + c];
            }
            __syncthreads();
            ln_apply4(uin, red, lmg, lmb, tid);
            int r = tid >> 6, j = (tid >> 1) & 31, ch = tid & 1;
            float acc = 0.f;
            #pragma unroll 8
            for (int ci = 0; ci < 128; ci++) {
                int c = ch + ci * 2;
                acc += uin[r * 256 + c] * slab[j * 258 + c];
            }
            acc += __shfl_xor_sync(0xffffffffu, acc, 1);
            if (ch == 0) {
                int jj = os * 32 + j, row = rg * 4 + r;
                g_h[row * 512 + jj] = gelu_f(acc + b1[jj]);
            }
        }
        group_bar(g);

        // ---- S3: slots = spre + h @ W2^T + b2 ----
        {
            #pragma unroll
            for (int i = 0; i < 8; i++) {
                int idx = i * 256 + tid; int r = idx >> 9, c = idx & 511;
                uin[r * 512 + c] = g_h[(rg * 4 + r) * 512 + c];
            }
            #pragma unroll
            for (int i = 0; i < 32; i++) {
                int idx = i * 256 + tid; int j = idx >> 9, c = idx & 511;
                slab[j * 516 + c] = W2[(size_t)(os * 16 + j) * 512 + c];
            }
            __syncthreads();
            int r = tid >> 6, j = (tid >> 2) & 15, cq = tid & 3;
            float acc = 0.f;
            #pragma unroll 8
            for (int ci = 0; ci < 128; ci++) {
                int c = cq + ci * 4;
                acc += uin[r * 512 + c] * slab[j * 516 + c];
            }
            acc += __shfl_xor_sync(0xffffffffu, acc, 1);
            acc += __shfl_xor_sync(0xffffffffu, acc, 2);
            if (cq == 0) {
                int d = os * 16 + j, row = rg * 4 + r;
                float val = acc + b2[d] + g_spre[row * 256 + d];
                g_slots[row * 256 + d] = val;
                if (last) out[row * 256 + d] = val;
            }
        }
        group_bar(g);

        if (!last) {
            qt_stage(smraw, rg, os, tid, lsg, lsb, 1);
            group_bar(g);
        } else {
            // ---- head: e = gelu(We1 @ slots + be1) -> g_qt reuse ----
            #pragma unroll
            for (int i = 0; i < 4; i++) {
                int idx = i * 256 + tid; int r = idx >> 8, c = idx & 255;
                uin[r * 256 + c] = g_slots[(rg * 4 + r) * 256 + c];
            }
            #pragma unroll
            for (int i = 0; i < 8; i++) {
                int idx = i * 256 + tid; int j = idx >> 8, c = idx & 255;
                slab[j * 264 + c] = We1[(size_t)(os * 8 + j) * 256 + c];
            }
            __syncthreads();
            int r = tid >> 6, j = (tid >> 3) & 7, c8 = tid & 7;
            float acc = 0.f;
            #pragma unroll 8
            for (int ci = 0; ci < 32; ci++) {
                int c = c8 + ci * 8;
                acc += uin[r * 256 + c] * slab[j * 264 + c];
            }
            acc += __shfl_xor_sync(0xffffffffu, acc, 1);
            acc += __shfl_xor_sync(0xffffffffu, acc, 2);
            acc += __shfl_xor_sync(0xffffffffu, acc, 4);
            if (c8 == 0) {
                int jj = os * 8 + j, row = rg * 4 + r;
                g_qt[row * 256 + jj] = gelu_f(acc + be1[jj]);
            }
            group_bar(g);
            if (gb == 0 && tid < 16) {
                int row = rg * 4 + (tid >> 2), p = tid & 3;
                float a2 = 0.f;
                #pragma unroll 8
                for (int k2 = 0; k2 < 32; k2++) {
                    int j2 = p + k2 * 4;
                    a2 += g_qt[row * 256 + j2] * We2[j2];
                }
                a2 += __shfl_xor_sync(0x0000ffffu, a2, 1);
                a2 += __shfl_xor_sync(0x0000ffffu, a2, 2);
                if (p == 0)
                    out[BB * KK * CC + row] = 1.0f / (1.0f + expf(-(a2 + be2[0])));
            }
        }
    }
}

// ---------------- host ----------------
extern "C" void kernel_launch(void* const* d_in, const int* in_sizes, int n_in,
                              void* d_out, int out_size) {
    const float* x        = (const float*)d_in[0];
    const float* noise    = (const float*)d_in[1];
    const float* slot_mu  = (const float*)d_in[2];
    const float* slot_ls  = (const float*)d_in[3];
    const float* ln_in_g  = (const float*)d_in[4];
    const float* ln_in_b  = (const float*)d_in[5];
    const float* ln_sl_g  = (const float*)d_in[6];
    const float* ln_sl_b  = (const float*)d_in[7];
    const float* ln_mlp_g = (const float*)d_in[8];
    const float* ln_mlp_b = (const float*)d_in[9];
    const float* Wq = (const float*)d_in[10];
    const float* bq = (const float*)d_in[11];
    const float* Wk = (const float*)d_in[12];
    const float* bk = (const float*)d_in[13];
    const float* Wv = (const float*)d_in[14];
    const float* bv = (const float*)d_in[15];
    const float* Wu = (const float*)d_in[16];
    const float* bu = (const float*)d_in[17];
    const float* W1 = (const float*)d_in[18];
    const float* b1 = (const float*)d_in[19];
    const float* W2 = (const float*)d_in[20];
    const float* b2 = (const float*)d_in[21];
    const float* We1 = (const float*)d_in[22];
    const float* be1 = (const float*)d_in[23];
    const float* We2 = (const float*)d_in[24];
    const float* be2 = (const float*)d_in[25];
    float* out = (float*)d_out;

    static int attr_set = 0;
    if (!attr_set) {
        cudaFuncSetAttribute(k_mega, cudaFuncAttributeMaxDynamicSharedMemorySize,
                             SMEM_ATTN);
        attr_set = 1;
    }

    k_mega<<<NBLK, 256, SMEM_ATTN>>>(x, ln_in_g, ln_in_b,
                                     slot_mu, slot_ls, noise,
                                     ln_sl_g, ln_sl_b, ln_mlp_g, ln_mlp_b,
                                     Wq, bq, Wk, bk, Wv, bv, Wu, bu,
                                     W1, b1, W2, b2,
                                     We1, be1, We2, be2, out);
}

// round 15
// speedup vs baseline: 1.0122x; 1.0122x over previous
#include <cuda_runtime.h>
#include <cuda_fp16.h>
#include <cstdint>
#include <math.h>

#define BB   16
#define CC   256
#define HWN  4096
#define KK   4
#define HIDN 512
#define EPS_W 1e-8f
#define LN_EPS 1e-5f
#define SCALE 0.0625f   // C^-0.5 = 1/16
#define NBLK 256
#define NGRP 16
#define GBLK 16

// ---------------- scratch (static device globals; no allocation) ----------------
static __device__ __align__(16) __half g_xnl [BB*HWN*CC];  // LN'd input (b,n,c) fp16
static __device__ __align__(16) float g_slots[BB*KK*CC];
static __device__ __align__(16) float g_qt  [BB*KK*CC];
static __device__            float g_qb  [BB*KK];
static __device__ __align__(16) float g_A   [BB*KK*CC];
static __device__            float g_S   [BB*KK];
static __device__ __align__(16) float g_spre[BB*KK*CC];
static __device__ __align__(16) float g_h   [BB*KK*HIDN];
static __device__ __align__(16) float g_Wvu [CC*CC];   // (Wu2@Wv)[d][c]
static __device__            float g_bvu [CC];
static __device__ __align__(16) float g_Wqk [CC*CC];   // scale*(Wk^T Wq)[c_out][e]
static __device__            float g_qtb [CC];
static __device__ __align__(16) float g_wqbk[CC];
static __device__            float g_bqbk;

// global barrier (phase 0 only)
static __device__ unsigned int g_bar_count = 0;
static __device__ volatile unsigned int g_bar_gen = 0;
// per-group barriers, 64B apart
static __device__ unsigned int g_gcount[NGRP * 16];
static __device__ volatile unsigned int g_ggen[NGRP * 16];

// dynamic smem layout for attn phase (bytes); tile = 128 tokens, x stride 133
#define SX_WORDS   (128 * 133)
#define OFF_SX     0
#define OFF_QT     (SX_WORDS * 4)
#define OFF_PART   (OFF_QT + 4 * 128 * 8)
#define OFF_SA     (OFF_PART + 256 * 16)
#define OFF_QB     (OFF_SA + 128 * 16)
#define OFF_SRED   (OFF_QB + 16)
#define SMEM_ATTN  (OFF_SRED + 16 * 4 + 16)

// update-phase view
#define U_OFF_IN    0
#define U_OFF_IN2   8192
#define U_OFF_SLAB  12288
#define U_OFF_RED   49152

__device__ __forceinline__ float gelu_f(float x) {
    return 0.5f * x * (1.0f + erff(x * 0.70710678118654752f));
}

__device__ __forceinline__ void grid_bar() {
    __syncthreads();
    if (threadIdx.x == 0) {
        __threadfence();
        unsigned int gen = g_bar_gen;
        if (atomicAdd(&g_bar_count, 1u) == NBLK - 1) {
            atomicExch(&g_bar_count, 0u);
            __threadfence();
            g_bar_gen = gen + 1;
        } else {
            while (g_bar_gen == gen) { __nanosleep(64); }
        }
        __threadfence();
    }
    __syncthreads();
}

__device__ __forceinline__ void group_bar(int g) {
    __syncthreads();
    if (threadIdx.x == 0) {
        __threadfence();
        unsigned int gen = g_ggen[g * 16];
        if (atomicAdd(&g_gcount[g * 16], 1u) == GBLK - 1) {
            atomicExch(&g_gcount[g * 16], 0u);
            __threadfence();
            g_ggen[g * 16] = gen + 1;
        } else {
            while (g_ggen[g * 16] == gen) { __nanosleep(32); }
        }
        __threadfence();
    }
    __syncthreads();
}

// LN of 4 rows (stride 256) in smem `sin`, in place; red = 256-float scratch.
__device__ __forceinline__ void ln_apply4(float* sin, float* red,
                                          const float* __restrict__ gg,
                                          const float* __restrict__ bb, int tid) {
    int r = tid >> 6, t = tid & 63;
    float4 v = ((const float4*)(sin + r * 256))[t];
    float s = v.x + v.y + v.z + v.w;
    float q = v.x * v.x + v.y * v.y + v.z * v.z + v.w * v.w;
    #pragma unroll
    for (int off = 16; off; off >>= 1) {
        s += __shfl_xor_sync(0xffffffffu, s, off);
        q += __shfl_xor_sync(0xffffffffu, q, off);
    }
    int w = tid >> 5;
    if ((tid & 31) == 0) { red[w * 2] = s; red[w * 2 + 1] = q; }
    __syncthreads();
    if (tid < 4) {
        float S = red[tid * 4] + red[tid * 4 + 2];
        float Q = red[tid * 4 + 1] + red[tid * 4 + 3];
        float m = S * (1.0f / 256.0f);
        red[16 + tid * 2] = m;
        red[17 + tid * 2] = rsqrtf(Q * (1.0f / 256.0f) - m * m + LN_EPS);
    }
    __syncthreads();
    #pragma unroll
    for (int i = 0; i < 4; i++) {
        int idx = i * 256 + tid; int rr = idx >> 8, c = idx & 255;
        float m = red[16 + rr * 2], rstd = red[17 + rr * 2];
        sin[rr * 256 + c] = (sin[rr * 256 + c] - m) * rstd * gg[c] + bb[c];
    }
    __syncthreads();
}

// ---------------- phase-0 device fns ----------------
__device__ void prep_unit(int bid, char* smraw, int tid,
                          const float* __restrict__ Wq, const float* __restrict__ Wk,
                          const float* __restrict__ bq, const float* __restrict__ Wv,
                          const float* __restrict__ bv, const float* __restrict__ Wu) {
    float* sbuf = (float*)smraw;               // 32*260
    float* wcs  = sbuf + 32 * 260;             // 1024 floats
    if (bid < 64) {
        int d0 = bid * 4;
        for (int idx = tid; idx < CC * 4; idx += 256) {
            int dl = idx & 3, e = idx >> 2;
            wcs[e * 4 + dl] = Wu[(size_t)(d0 + dl) * 512 + 256 + e];
        }
        __syncthreads();
        float a0 = 0.f, a1 = 0.f, a2 = 0.f, a3 = 0.f;
        for (int ch = 0; ch < 8; ch++) {
            #pragma unroll 8
            for (int it = 0; it < 32; it++)
                sbuf[it * 260 + tid] = Wv[(size_t)(ch * 32 + it) * CC + tid];
            __syncthreads();
            #pragma unroll 8
            for (int el = 0; el < 32; el++) {
                float x = sbuf[el * 260 + tid];
                float4 w = *(const float4*)&wcs[(ch * 32 + el) * 4];
                a0 += w.x * x; a1 += w.y * x; a2 += w.z * x; a3 += w.w * x;
            }
            __syncthreads();
        }
        g_Wvu[(size_t)(d0 + 0) * CC + tid] = a0;
        g_Wvu[(size_t)(d0 + 1) * CC + tid] = a1;
        g_Wvu[(size_t)(d0 + 2) * CC + tid] = a2;
        g_Wvu[(size_t)(d0 + 3) * CC + tid] = a3;
        if (tid < 4) {
            float s = 0.f;
            for (int e = 0; e < CC; e++)
                s += Wu[(size_t)(d0 + tid) * 512 + 256 + e] * bv[e];
            g_bvu[d0 + tid] = s;
        }
    } else {
        int c0 = (bid - 64) * 4;
        float a0 = 0.f, a1 = 0.f, a2 = 0.f, a3 = 0.f;
        for (int ch = 0; ch < 8; ch++) {
            #pragma unroll 8
            for (int it = 0; it < 32; it++)
                sbuf[it * 260 + tid] = Wq[(size_t)(ch * 32 + it) * CC + tid];
            if (tid < 128) {
                int dl = tid >> 2, cl = tid & 3;
                wcs[dl * 4 + cl] = Wk[(size_t)(ch * 32 + dl) * CC + c0 + cl];
            }
            __syncthreads();
            #pragma unroll 8
            for (int dl = 0; dl < 32; dl++) {
                float x = sbuf[dl * 260 + tid];
                a0 += wcs[dl * 4 + 0] * x; a1 += wcs[dl * 4 + 1] * x;
                a2 += wcs[dl * 4 + 2] * x; a3 += wcs[dl * 4 + 3] * x;
            }
            __syncthreads();
        }
        g_Wqk[(size_t)(c0 + 0) * CC + tid] = SCALE * a0;
        g_Wqk[(size_t)(c0 + 1) * CC + tid] = SCALE * a1;
        g_Wqk[(size_t)(c0 + 2) * CC + tid] = SCALE * a2;
        g_Wqk[(size_t)(c0 + 3) * CC + tid] = SCALE * a3;
        if (tid < 4) {
            float s = 0.f;
            for (int d = 0; d < CC; d++) s += Wk[(size_t)d * CC + c0 + tid] * bq[d];
            g_qtb[c0 + tid] = SCALE * s;
        }
    }
    __syncthreads();
}

__device__ void prep_bias(char* smraw, int tid,
                          const float* __restrict__ Wq, const float* __restrict__ bq,
                          const float* __restrict__ bk) {
    float* sbuf = (float*)smraw;
    float s = 0.f;
    #pragma unroll 8
    for (int d = 0; d < CC; d++) s += Wq[(size_t)d * CC + tid] * bk[d];
    g_wqbk[tid] = SCALE * s;
    sbuf[tid] = bq[tid] * bk[tid];
    __syncthreads();
    #pragma unroll
    for (int st = 128; st > 0; st >>= 1) {
        if (tid < st) sbuf[tid] += sbuf[tid + st];
        __syncthreads();
    }
    if (tid == 0) g_bqbk = SCALE * sbuf[0];
    __syncthreads();
}

// one LN-input tile (32 tokens): t in [0,2048)
__device__ void ln_tile(int t, char* smraw, int tid,
                        const float* __restrict__ x,
                        const float* __restrict__ lg,
                        const float* __restrict__ lb) {
    float* sm = (float*)smraw;        // 256*33
    float* ps = sm + 256 * 33;
    float* pq = ps + 256;
    float* mu = pq + 256;
    float* rs = mu + 32;
    int b = t >> 7;
    int tile = t & 127;
    int n0 = tile * 32;
    __syncthreads();

    const float* xb = x + ((size_t)b * CC) * HWN + n0;
    #pragma unroll 8
    for (int it = 0; it < 32; it++) {
        int idx = it * 256 + tid;
        int n = idx & 31, c = idx >> 5;
        sm[c * 33 + n] = xb[(size_t)c * HWN + n];
    }
    __syncthreads();

    int p = tid >> 5, tn = tid & 31;
    float s = 0.f, sq = 0.f;
    #pragma unroll 8
    for (int cc = 0; cc < 32; cc++) {
        float v = sm[(p * 32 + cc) * 33 + tn];
        s += v; sq += v * v;
    }
    ps[p * 32 + tn] = s; pq[p * 32 + tn] = sq;
    __syncthreads();
    if (tid < 32) {
        float S = 0.f, Q = 0.f;
        #pragma unroll
        for (int i = 0; i < 8; i++) { S += ps[i * 32 + tid]; Q += pq[i * 32 + tid]; }
        float m = S * (1.0f / 256.0f);
        float var = Q * (1.0f / 256.0f) - m * m;
        mu[tid] = m;
        rs[tid] = rsqrtf(var + LN_EPS);
    }
    __syncthreads();

    float gc = lg[tid], bc = lb[tid];
    __half* out = g_xnl + ((size_t)(b * HWN + n0)) * CC;
    #pragma unroll 8
    for (int it = 0; it < 32; it++) {
        float v = sm[tid * 33 + it];
        out[(size_t)it * CC + tid] = __float2half_rn((v - mu[it]) * rs[it] * gc + bc);
    }
}

// ---------------- attn tile (R9 body, packed qt) ----------------
__device__ __forceinline__ void attn_tile(int t, char* smraw, int tid) {
    unsigned int* sx = (unsigned int*)(smraw + OFF_SX);
    float*  sqtf  = (float*) (smraw + OFF_QT);
    float*  spart = (float*) (smraw + OFF_PART);
    float*  sa    = (float*) (smraw + OFF_SA);
    float*  sqb   = (float*) (smraw + OFF_QB);
    float*  sred  = (float*) (smraw + OFF_SRED);

    int b = t >> 5;
    int tile = t & 31;
    int n0 = tile * 128;

    const uint4* gx = (const uint4*)(g_xnl + ((size_t)(b * HWN + n0)) * CC);
    #pragma unroll
    for (int it = 0; it < 16; it++) {
        int idx = it * 256 + tid;
        int n = idx >> 5, c8 = idx & 31;
        uint4 u = gx[idx];
        unsigned int* dst = sx + n * 133 + c8 * 4;
        dst[0] = u.x; dst[1] = u.y; dst[2] = u.z; dst[3] = u.w;
    }
    #pragma unroll
    for (int it = 0; it < 4; it++) {
        int idx = it * 256 + tid;
        int k = idx & 3, sub = (idx >> 2) & 1, c2 = idx >> 3;
        sqtf[c2 * 8 + sub * 4 + k] = g_qt[(b * KK + k) * CC + c2 * 2 + sub];
    }
    if (tid < 4) sqb[tid] = g_qb[b * KK + tid];
    __syncthreads();

    {
        int n = tid & 127, h = tid >> 7;
        const unsigned int* xrow = sx + n * 133 + h * 64;
        const float4* q4 = (const float4*)sqtf + h * 128;
        float p0 = 0.f, p1 = 0.f, p2 = 0.f, p3 = 0.f;
        #pragma unroll 8
        for (int i = 0; i < 64; i++) {
            __half2 hx = *(const __half2*)&xrow[i];
            float2 xf = __half22float2(hx);
            float4 qa = q4[2 * i];
            float4 qb = q4[2 * i + 1];
            p0 += xf.x * qa.x + xf.y * qb.x;
            p1 += xf.x * qa.y + xf.y * qb.y;
            p2 += xf.x * qa.z + xf.y * qb.z;
            p3 += xf.x * qa.w + xf.y * qb.w;
        }
        ((float4*)spart)[tid] = make_float4(p0, p1, p2, p3);
    }
    __syncthreads();

    if (tid < 128) {
        float4 pa = ((const float4*)spart)[tid];
        float4 pb = ((const float4*)spart)[tid + 128];
        float l0 = pa.x + pb.x + sqb[0];
        float l1 = pa.y + pb.y + sqb[1];
        float l2 = pa.z + pb.z + sqb[2];
        float l3 = pa.w + pb.w + sqb[3];
        float mx = fmaxf(fmaxf(l0, l1), fmaxf(l2, l3));
        float e0 = __expf(l0 - mx), e1 = __expf(l1 - mx);
        float e2 = __expf(l2 - mx), e3 = __expf(l3 - mx);
        float inv = __fdividef(1.0f, e0 + e1 + e2 + e3);
        float a0 = e0 * inv, a1 = e1 * inv, a2 = e2 * inv, a3 = e3 * inv;
        ((float4*)sa)[tid] = make_float4(a0, a1, a2, a3);
        float s0 = a0, s1 = a1, s2 = a2, s3 = a3;
        #pragma unroll
        for (int off = 16; off; off >>= 1) {
            s0 += __shfl_xor_sync(0xffffffffu, s0, off);
            s1 += __shfl_xor_sync(0xffffffffu, s1, off);
            s2 += __shfl_xor_sync(0xffffffffu, s2, off);
            s3 += __shfl_xor_sync(0xffffffffu, s3, off);
        }
        if ((tid & 31) == 0) {
            int w = tid >> 5;
            sred[w * 4 + 0] = s0; sred[w * 4 + 1] = s1;
            sred[w * 4 + 2] = s2; sred[w * 4 + 3] = s3;
        }
    }
    __syncthreads();
    if (tid < 4) {
        float s = sred[tid] + sred[4 + tid] + sred[8 + tid] + sred[12 + tid];
        atomicAdd(&g_S[b * KK + tid], s);
    }

    {
        int w = tid >> 5, L = tid & 31;
        int word = w * 16 + (L & 15);
        bool hi = (L >= 16);
        float2 a0 = {0.f, 0.f}, a1 = {0.f, 0.f}, a2 = {0.f, 0.f}, a3 = {0.f, 0.f};
        #pragma unroll 8
        for (int t2 = 0; t2 < 64; t2++) {
            int nn = hi ? (64 + ((t2 + 16) & 63)) : t2;
            __half2 hx = *(const __half2*)&sx[nn * 133 + word];
            float2 xf = __half22float2(hx);
            float4 av = ((const float4*)sa)[nn];
            a0.x += av.x * xf.x; a0.y += av.x * xf.y;
            a1.x += av.y * xf.x; a1.y += av.y * xf.y;
            a2.x += av.z * xf.x; a2.y += av.z * xf.y;
            a3.x += av.w * xf.x; a3.y += av.w * xf.y;
        }
        a0.x += __shfl_down_sync(0xffffffffu, a0.x, 16);
        a0.y += __shfl_down_sync(0xffffffffu, a0.y, 16);
        a1.x += __shfl_down_sync(0xffffffffu, a1.x, 16);
        a1.y += __shfl_down_sync(0xffffffffu, a1.y, 16);
        a2.x += __shfl_down_sync(0xffffffffu, a2.x, 16);
        a2.y += __shfl_down_sync(0xffffffffu, a2.y, 16);
        a3.x += __shfl_down_sync(0xffffffffu, a3.x, 16);
        a3.y += __shfl_down_sync(0xffffffffu, a3.y, 16);
        if (!hi) {
            int c = 2 * word;
            float* A0 = g_A + (b * KK + 0) * CC + c;
            float* A1 = g_A + (b * KK + 1) * CC + c;
            float* A2 = g_A + (b * KK + 2) * CC + c;
            float* A3 = g_A + (b * KK + 3) * CC + c;
            atomicAdd(A0, a0.x); atomicAdd(A0 + 1, a0.y);
            atomicAdd(A1, a1.x); atomicAdd(A1 + 1, a1.y);
            atomicAdd(A2, a2.x); atomicAdd(A2 + 1, a2.y);
            atomicAdd(A3, a3.x); atomicAdd(A3 + 1, a3.y);
        }
    }
    __syncthreads();
}

// ---------------- qt stage (rg = group, os = in-group block) ----------------
__device__ __forceinline__ void qt_stage(char* smraw, int rg, int os, int tid,
                                         const float* lsg, const float* lsb,
                                         int zeroAS) {
    float* uin  = (float*)(smraw + U_OFF_IN);
    float* slab = (float*)(smraw + U_OFF_SLAB);
    float* red  = (float*)(smraw + U_OFF_RED);

    #pragma unroll
    for (int i = 0; i < 4; i++) {
        int idx = i * 256 + tid; int r = idx >> 8, c = idx & 255;
        uin[r * 256 + c] = g_slots[(rg * 4 + r) * 256 + c];
    }
    #pragma unroll
    for (int i = 0; i < 16; i++) {
        int idx = i * 256 + tid; int j = idx >> 8, c = idx & 255;
        slab[j * 260 + c] = g_Wqk[(size_t)(os * 16 + j) * 256 + c];
    }
    __syncthreads();
    ln_apply4(uin, red, lsg, lsb, tid);

    if (os == 0) {
        int r = tid >> 6, t = tid & 63;
        float4 v = ((const float4*)(uin + r * 256))[t];
        float4 w = ((const float4*)g_wqbk)[t];
        float s = v.x * w.x + v.y * w.y + v.z * w.z + v.w * w.w;
        #pragma unroll
        for (int off = 16; off; off >>= 1) s += __shfl_xor_sync(0xffffffffu, s, off);
        if ((tid & 31) == 0) red[(tid >> 5) * 2] = s;
        __syncthreads();
        if (tid < 4) g_qb[rg * 4 + tid] = red[tid * 4] + red[tid * 4 + 2] + g_bqbk;
    }

    int r = tid >> 6, j = (tid >> 2) & 15, cq = tid & 3;
    float acc = 0.f;
    #pragma unroll 8
    for (int ci = 0; ci < 64; ci++) {
        int c = cq + ci * 4;
        acc += uin[r * 256 + c] * slab[j * 260 + c];
    }
    acc += __shfl_xor_sync(0xffffffffu, acc, 1);
    acc += __shfl_xor_sync(0xffffffffu, acc, 2);
    if (cq == 0) {
        int cc = os * 16 + j, row = rg * 4 + r;
        g_qt[row * 256 + cc] = acc + g_qtb[cc];
    }
    if (zeroAS) {
        if (tid < 64) {
            int r2 = tid >> 4, j2 = tid & 15;
            g_A[(rg * 4 + r2) * 256 + os * 16 + j2] = 0.f;
        }
        if (os == 0 && tid < 4) g_S[rg * 4 + tid] = 0.f;
    }
}

// ---------------- THE kernel ----------------
__global__ void __launch_bounds__(256, 2) k_mega(
    const float* __restrict__ x,
    const float* __restrict__ lig,  const float* __restrict__ lib,
    const float* __restrict__ smu,  const float* __restrict__ sls,
    const float* __restrict__ noise,
    const float* __restrict__ lsg,  const float* __restrict__ lsb,
    const float* __restrict__ lmg,  const float* __restrict__ lmb,
    const float* __restrict__ Wq,   const float* __restrict__ bq,
    const float* __restrict__ Wk,   const float* __restrict__ bk,
    const float* __restrict__ Wv,   const float* __restrict__ bv,
    const float* __restrict__ Wu,   const float* __restrict__ bu,
    const float* __restrict__ W1,   const float* __restrict__ b1,
    const float* __restrict__ W2,   const float* __restrict__ b2,
    const float* __restrict__ We1,  const float* __restrict__ be1,
    const float* __restrict__ We2,  const float* __restrict__ be2,
    float* __restrict__ out) {
    extern __shared__ __align__(16) char smraw[];
    float* uin  = (float*)(smraw + U_OFF_IN);
    float* uin2 = (float*)(smraw + U_OFF_IN2);
    float* slab = (float*)(smraw + U_OFF_SLAB);
    float* slab2 = slab + 16 * 260;
    float* red  = (float*)(smraw + U_OFF_RED);
    int bid = blockIdx.x;
    int tid = threadIdx.x;
    int g  = bid >> 4;          // group = batch element
    int gb = bid & 15;          // block within group
    int rg = g, os = gb;

    // ================= phase 0 (global) =================
    if (bid < 128) {
        prep_unit(bid, smraw, tid, Wq, Wk, bq, Wv, bv, Wu);
    } else if (bid == 128) {
        prep_bias(smraw, tid, Wq, bq, bk);
    } else if (bid < 193) {
        int row = bid - 129;
        float ns = smu[tid] + expf(sls[tid]) * noise[row * 256 + tid];
        g_slots[row * 256 + tid] = ns;
        g_A[row * 256 + tid] = 0.f;
        if (tid == 0) g_S[row] = 0.f;
    }
    if (bid <= 128) {
        #pragma unroll
        for (int i = 0; i < 4; i++) ln_tile(bid * 4 + i, smraw, tid, x, lig, lib);
    } else {
        for (int t = 516 + (bid - 129); t < 2048; t += 127)
            ln_tile(t, smraw, tid, x, lig, lib);
    }
    grid_bar();

    // ================= per-group pipeline =================
    qt_stage(smraw, rg, os, tid, lsg, lsb, 0);
    group_bar(g);

    for (int it = 0; it < 3; it++) {
        int last = (it == 2);
        // attn: this group's batch only; tiles g*32 + gb*2, +1
        attn_tile(g * 32 + gb * 2, smraw, tid);
        attn_tile(g * 32 + gb * 2 + 1, smraw, tid);
        group_bar(g);

        // ---- S1: spre ----
        {
            #pragma unroll
            for (int i = 0; i < 4; i++) {
                int idx = i * 256 + tid; int r = idx >> 8, c = idx & 255;
                int row = rg * 4 + r;
                uin[r * 256 + c] = g_slots[row * 256 + c];
                float Sv = g_S[row];
                uin2[r * 256 + c] = g_A[row * 256 + c] * (1.0f / (Sv + EPS_W));
            }
            #pragma unroll
            for (int i = 0; i < 16; i++) {
                int idx = i * 256 + tid; int j = idx >> 8, c = idx & 255;
                slab [j * 260 + c] = Wu[(size_t)(os * 16 + j) * 512 + c];
                slab2[j * 260 + c] = g_Wvu[(size_t)(os * 16 + j) * 256 + c];
            }
            __syncthreads();
            int r = tid >> 6, j = (tid >> 2) & 15, cq = tid & 3;
            float acc = 0.f;
            #pragma unroll 8
            for (int ci = 0; ci < 64; ci++) {
                int c = cq + ci * 4;
                acc += uin[r * 256 + c] * slab[j * 260 + c]
                     + uin2[r * 256 + c] * slab2[j * 260 + c];
            }
            acc += __shfl_xor_sync(0xffffffffu, acc, 1);
            acc += __shfl_xor_sync(0xffffffffu, acc, 2);
            if (cq == 0) {
                int d = os * 16 + j, row = rg * 4 + r;
                float Sv = g_S[row];
                float beta = Sv / (Sv + EPS_W);
                g_spre[row * 256 + d] = acc + bu[d] + uin[r * 256 + d]
                                      + beta * g_bvu[d];
            }
        }
        group_bar(g);

        // ---- S2: h = gelu(LN_mlp(spre) @ W1^T + b1) ----
        {
            #pragma unroll
            for (int i = 0; i < 4; i++) {
                int idx = i * 256 + tid; int r = idx >> 8, c = idx & 255;
                uin[r * 256 + c] = g_spre[(rg * 4 + r) * 256 + c];
            }
            #pragma unroll
            for (int i = 0; i < 32; i++) {
                int idx = i * 256 + tid; int j = idx >> 8, c = idx & 255;
                slab[j * 258 + c] = W1[(size_t)(os * 32 + j) * 256 + c];
            }
            __syncthreads();
            ln_apply4(uin, red, lmg, lmb, tid);
            int r = tid >> 6, j = (tid >> 1) & 31, ch = tid & 1;
            float acc = 0.f;
            #pragma unroll 8
            for (int ci = 0; ci < 128; ci++) {
                int c = ch + ci * 2;
                acc += uin[r * 256 + c] * slab[j * 258 + c];
            }
            acc += __shfl_xor_sync(0xffffffffu, acc, 1);
            if (ch == 0) {
                int jj = os * 32 + j, row = rg * 4 + r;
                g_h[row * 512 + jj] = gelu_f(acc + b1[jj]);
            }
        }
        group_bar(g);

        // ---- S3: slots = spre + h @ W2^T + b2 ----
        {
            #pragma unroll
            for (int i = 0; i < 8; i++) {
                int idx = i * 256 + tid; int r = idx >> 9, c = idx & 511;
                uin[r * 512 + c] = g_h[(rg * 4 + r) * 512 + c];
            }
            #pragma unroll
            for (int i = 0; i < 32; i++) {
                int idx = i * 256 + tid; int j = idx >> 9, c = idx & 511;
                slab[j * 516 + c] = W2[(size_t)(os * 16 + j) * 512 + c];
            }
            __syncthreads();
            int r = tid >> 6, j = (tid >> 2) & 15, cq = tid & 3;
            float acc = 0.f;
            #pragma unroll 8
            for (int ci = 0; ci < 128; ci++) {
                int c = cq + ci * 4;
                acc += uin[r * 512 + c] * slab[j * 516 + c];
            }
            acc += __shfl_xor_sync(0xffffffffu, acc, 1);
            acc += __shfl_xor_sync(0xffffffffu, acc, 2);
            if (cq == 0) {
                int d = os * 16 + j, row = rg * 4 + r;
                float val = acc + b2[d] + g_spre[row * 256 + d];
                g_slots[row * 256 + d] = val;
                if (last) out[row * 256 + d] = val;
            }
        }
        group_bar(g);

        if (!last) {
            qt_stage(smraw, rg, os, tid, lsg, lsb, 1);
            group_bar(g);
        } else {
            // ---- head: e = gelu(We1 @ slots + be1) -> g_qt reuse ----
            #pragma unroll
            for (int i = 0; i < 4; i++) {
                int idx = i * 256 + tid; int r = idx >> 8, c = idx & 255;
                uin[r * 256 + c] = g_slots[(rg * 4 + r) * 256 + c];
            }
            #pragma unroll
            for (int i = 0; i < 8; i++) {
                int idx = i * 256 + tid; int j = idx >> 8, c = idx & 255;
                slab[j * 264 + c] = We1[(size_t)(os * 8 + j) * 256 + c];
            }
            __syncthreads();
            int r = tid >> 6, j = (tid >> 3) & 7, c8 = tid & 7;
            float acc = 0.f;
            #pragma unroll 8
            for (int ci = 0; ci < 32; ci++) {
                int c = c8 + ci * 8;
                acc += uin[r * 256 + c] * slab[j * 264 + c];
            }
            acc += __shfl_xor_sync(0xffffffffu, acc, 1);
            acc += __shfl_xor_sync(0xffffffffu, acc, 2);
            acc += __shfl_xor_sync(0xffffffffu, acc, 4);
            if (c8 == 0) {
                int jj = os * 8 + j, row = rg * 4 + r;
                g_qt[row * 256 + jj] = gelu_f(acc + be1[jj]);
            }
            group_bar(g);
            if (gb == 0 && tid < 16) {
                int row = rg * 4 + (tid >> 2), p = tid & 3;
                float a2 = 0.f;
                #pragma unroll 8
                for (int k2 = 0; k2 < 32; k2++) {
                    int j2 = p + k2 * 4;
                    a2 += g_qt[row * 256 + j2] * We2[j2];
                }
                a2 += __shfl_xor_sync(0x0000ffffu, a2, 1);
                a2 += __shfl_xor_sync(0x0000ffffu, a2, 2);
                if (p == 0)
                    out[BB * KK * CC + row] = 1.0f / (1.0f + expf(-(a2 + be2[0])));
            }
        }
    }
}

// ---------------- host ----------------
extern "C" void kernel_launch(void* const* d_in, const int* in_sizes, int n_in,
                              void* d_out, int out_size) {
    const float* x        = (const float*)d_in[0];
    const float* noise    = (const float*)d_in[1];
    const float* slot_mu  = (const float*)d_in[2];
    const float* slot_ls  = (const float*)d_in[3];
    const float* ln_in_g  = (const float*)d_in[4];
    const float* ln_in_b  = (const float*)d_in[5];
    const float* ln_sl_g  = (const float*)d_in[6];
    const float* ln_sl_b  = (const float*)d_in[7];
    const float* ln_mlp_g = (const float*)d_in[8];
    const float* ln_mlp_b = (const float*)d_in[9];
    const float* Wq = (const float*)d_in[10];
    const float* bq = (const float*)d_in[11];
    const float* Wk = (const float*)d_in[12];
    const float* bk = (const float*)d_in[13];
    const float* Wv = (const float*)d_in[14];
    const float* bv = (const float*)d_in[15];
    const float* Wu = (const float*)d_in[16];
    const float* bu = (const float*)d_in[17];
    const float* W1 = (const float*)d_in[18];
    const float* b1 = (const float*)d_in[19];
    const float* W2 = (const float*)d_in[20];
    const float* b2 = (const float*)d_in[21];
    const float* We1 = (const float*)d_in[22];
    const float* be1 = (const float*)d_in[23];
    const float* We2 = (const float*)d_in[24];
    const float* be2 = (const float*)d_in[25];
    float* out = (float*)d_out;

    static int attr_set = 0;
    if (!attr_set) {
        cudaFuncSetAttribute(k_mega, cudaFuncAttributeMaxDynamicSharedMemorySize,
                             SMEM_ATTN);
        attr_set = 1;
    }

    k_mega<<<NBLK, 256, SMEM_ATTN>>>(x, ln_in_g, ln_in_b,
                                     slot_mu, slot_ls, noise,
                                     ln_sl_g, ln_sl_b, ln_mlp_g, ln_mlp_b,
                                     Wq, bq, Wk, bk, Wv, bv, Wu, bu,
                                     W1, b1, W2, b2,
                                     We1, be1, We2, be2, out);
}

// round 17
// speedup vs baseline: 1.1386x; 1.1249x over previous
#include <cuda_runtime.h>
#include <cuda_fp16.h>
#include <cstdint>
#include <math.h>

#define BB   16
#define CC   256
#define HWN  4096
#define KK   4
#define HIDN 512
#define EPS_W 1e-8f
#define LN_EPS 1e-5f
#define SCALE 0.0625f   // C^-0.5 = 1/16
#define NBLK 256

// ---------------- scratch (static device globals; no allocation) ----------------
static __device__ __align__(16) __half g_xnl [BB*HWN*CC];  // LN'd input (b,n,c) fp16
static __device__ __align__(16) float g_slots[BB*KK*CC];
static __device__ __align__(16) float g_qt  [BB*KK*CC];
static __device__            float g_qb  [BB*KK];
static __device__ __align__(16) float g_A   [BB*KK*CC];
static __device__            float g_S   [BB*KK];
static __device__ __align__(16) float g_spre[BB*KK*CC];
static __device__ __align__(16) float g_h   [BB*KK*HIDN];
static __device__ __align__(16) float g_Wvu [CC*CC];   // (Wu2@Wv)[d][c]
static __device__            float g_bvu [CC];
static __device__ __align__(16) float g_Wqk [CC*CC];   // scale*(Wk^T Wq)[c_out][e]
static __device__            float g_qtb [CC];
static __device__ __align__(16) float g_wqbk[CC];
static __device__            float g_bqbk;

// grid barrier state
static __device__ unsigned int g_bar_count = 0;
static __device__ volatile unsigned int g_bar_gen = 0;

// attn smem layout: x tile 128 tokens, 280 halves/row (140 words, 16B-aligned rows,
// 140 mod 32 = 12 -> ldmatrix 8-lane phases conflict-free)
#define XH 280
#define OFF_SX    0                 // 128*280*2 = 71680
#define OFF_BT1   71680             // 512 uint2 = 4096
#define OFF_BT2   75776             // 256 uint2 = 2048
#define OFF_SA    77824             // 256 u32   = 1024
#define OFF_QB    78848             // 16
#define OFF_SRED  78880             // 128
#define SMEM_DYN  79040

// update-phase view (same dynamic smem)
#define U_OFF_IN    0
#define U_OFF_IN2   8192
#define U_OFF_SLAB  12288
#define U_OFF_RED   49152

__device__ __forceinline__ float gelu_f(float x) {
    return 0.5f * x * (1.0f + erff(x * 0.70710678118654752f));
}

__device__ __forceinline__ unsigned packh2f(float lo, float hi) {
    __half2 h = __floats2half2_rn(lo, hi);
    return *reinterpret_cast<unsigned*>(&h);
}
__device__ __forceinline__ unsigned packh2h(__half lo, __half hi) {
    __half2 h = __halves2half2(lo, hi);
    return *reinterpret_cast<unsigned*>(&h);
}

__device__ __forceinline__ void ldm4(unsigned& r0, unsigned& r1,
                                     unsigned& r2, unsigned& r3, const void* p) {
    unsigned addr = (unsigned)__cvta_generic_to_shared(p);
    asm volatile("ldmatrix.sync.aligned.m8n8.x4.shared.b16 {%0,%1,%2,%3},[%4];"
                 : "=r"(r0), "=r"(r1), "=r"(r2), "=r"(r3) : "r"(addr));
}
__device__ __forceinline__ void ldm4t(unsigned& r0, unsigned& r1,
                                      unsigned& r2, unsigned& r3, const void* p) {
    unsigned addr = (unsigned)__cvta_generic_to_shared(p);
    asm volatile("ldmatrix.sync.aligned.m8n8.x4.trans.shared.b16 {%0,%1,%2,%3},[%4];"
                 : "=r"(r0), "=r"(r1), "=r"(r2), "=r"(r3) : "r"(addr));
}
__device__ __forceinline__ void mma16816(float* d, unsigned a0, unsigned a1,
                                         unsigned a2, unsigned a3,
                                         unsigned b0, unsigned b1) {
    asm volatile("mma.sync.aligned.m16n8k16.row.col.f32.f16.f16.f32 "
                 "{%0,%1,%2,%3}, {%4,%5,%6,%7}, {%8,%9}, {%0,%1,%2,%3};"
                 : "+f"(d[0]), "+f"(d[1]), "+f"(d[2]), "+f"(d[3])
                 : "r"(a0), "r"(a1), "r"(a2), "r"(a3), "r"(b0), "r"(b1));
}

__device__ __forceinline__ void grid_bar() {
    __syncthreads();
    if (threadIdx.x == 0) {
        __threadfence();
        unsigned int gen = g_bar_gen;
        if (atomicAdd(&g_bar_count, 1u) == NBLK - 1) {
            atomicExch(&g_bar_count, 0u);
            __threadfence();
            g_bar_gen = gen + 1;
        } else {
            while (g_bar_gen == gen) { __nanosleep(64); }
        }
        __threadfence();
    }
    __syncthreads();
}

// LN of 4 rows (stride 256) in smem `sin`, in place; red = 256-float scratch.
__device__ __forceinline__ void ln_apply4(float* sin, float* red,
                                          const float* __restrict__ gg,
                                          const float* __restrict__ bb, int tid) {
    int r = tid >> 6, t = tid & 63;
    float4 v = ((const float4*)(sin + r * 256))[t];
    float s = v.x + v.y + v.z + v.w;
    float q = v.x * v.x + v.y * v.y + v.z * v.z + v.w * v.w;
    #pragma unroll
    for (int off = 16; off; off >>= 1) {
        s += __shfl_xor_sync(0xffffffffu, s, off);
        q += __shfl_xor_sync(0xffffffffu, q, off);
    }
    int w = tid >> 5;
    if ((tid & 31) == 0) { red[w * 2] = s; red[w * 2 + 1] = q; }
    __syncthreads();
    if (tid < 4) {
        float S = red[tid * 4] + red[tid * 4 + 2];
        float Q = red[tid * 4 + 1] + red[tid * 4 + 3];
        float m = S * (1.0f / 256.0f);
        red[16 + tid * 2] = m;
        red[17 + tid * 2] = rsqrtf(Q * (1.0f / 256.0f) - m * m + LN_EPS);
    }
    __syncthreads();
    #pragma unroll
    for (int i = 0; i < 4; i++) {
        int idx = i * 256 + tid; int rr = idx >> 8, c = idx & 255;
        float m = red[16 + rr * 2], rstd = red[17 + rr * 2];
        sin[rr * 256 + c] = (sin[rr * 256 + c] - m) * rstd * gg[c] + bb[c];
    }
    __syncthreads();
}

// ---------------- phase-0 device fns ----------------
__device__ void prep_unit(int bid, char* smraw, int tid,
                          const float* __restrict__ Wq, const float* __restrict__ Wk,
                          const float* __restrict__ bq, const float* __restrict__ Wv,
                          const float* __restrict__ bv, const float* __restrict__ Wu) {
    float* sbuf = (float*)smraw;               // 32*260
    float* wcs  = sbuf + 32 * 260;             // 1024 floats
    if (bid < 64) {
        int d0 = bid * 4;
        for (int idx = tid; idx < CC * 4; idx += 256) {
            int dl = idx & 3, e = idx >> 2;
            wcs[e * 4 + dl] = Wu[(size_t)(d0 + dl) * 512 + 256 + e];
        }
        __syncthreads();
        float a0 = 0.f, a1 = 0.f, a2 = 0.f, a3 = 0.f;
        for (int ch = 0; ch < 8; ch++) {
            #pragma unroll 8
            for (int it = 0; it < 32; it++)
                sbuf[it * 260 + tid] = Wv[(size_t)(ch * 32 + it) * CC + tid];
            __syncthreads();
            #pragma unroll 8
            for (int el = 0; el < 32; el++) {
                float x = sbuf[el * 260 + tid];
                float4 w = *(const float4*)&wcs[(ch * 32 + el) * 4];
                a0 += w.x * x; a1 += w.y * x; a2 += w.z * x; a3 += w.w * x;
            }
            __syncthreads();
        }
        g_Wvu[(size_t)(d0 + 0) * CC + tid] = a0;
        g_Wvu[(size_t)(d0 + 1) * CC + tid] = a1;
        g_Wvu[(size_t)(d0 + 2) * CC + tid] = a2;
        g_Wvu[(size_t)(d0 + 3) * CC + tid] = a3;
        if (tid < 4) {
            float s = 0.f;
            for (int e = 0; e < CC; e++)
                s += Wu[(size_t)(d0 + tid) * 512 + 256 + e] * bv[e];
            g_bvu[d0 + tid] = s;
        }
    } else {
        int c0 = (bid - 64) * 4;
        float a0 = 0.f, a1 = 0.f, a2 = 0.f, a3 = 0.f;
        for (int ch = 0; ch < 8; ch++) {
            #pragma unroll 8
            for (int it = 0; it < 32; it++)
                sbuf[it * 260 + tid] = Wq[(size_t)(ch * 32 + it) * CC + tid];
            if (tid < 128) {
                int dl = tid >> 2, cl = tid & 3;
                wcs[dl * 4 + cl] = Wk[(size_t)(ch * 32 + dl) * CC + c0 + cl];
            }
            __syncthreads();
            #pragma unroll 8
            for (int dl = 0; dl < 32; dl++) {
                float x = sbuf[dl * 260 + tid];
                a0 += wcs[dl * 4 + 0] * x; a1 += wcs[dl * 4 + 1] * x;
                a2 += wcs[dl * 4 + 2] * x; a3 += wcs[dl * 4 + 3] * x;
            }
            __syncthreads();
        }
        g_Wqk[(size_t)(c0 + 0) * CC + tid] = SCALE * a0;
        g_Wqk[(size_t)(c0 + 1) * CC + tid] = SCALE * a1;
        g_Wqk[(size_t)(c0 + 2) * CC + tid] = SCALE * a2;
        g_Wqk[(size_t)(c0 + 3) * CC + tid] = SCALE * a3;
        if (tid < 4) {
            float s = 0.f;
            for (int d = 0; d < CC; d++) s += Wk[(size_t)d * CC + c0 + tid] * bq[d];
            g_qtb[c0 + tid] = SCALE * s;
        }
    }
    __syncthreads();
}

__device__ void prep_bias(char* smraw, int tid,
                          const float* __restrict__ Wq, const float* __restrict__ bq,
                          const float* __restrict__ bk) {
    float* sbuf = (float*)smraw;
    float s = 0.f;
    #pragma unroll 8
    for (int d = 0; d < CC; d++) s += Wq[(size_t)d * CC + tid] * bk[d];
    g_wqbk[tid] = SCALE * s;
    sbuf[tid] = bq[tid] * bk[tid];
    __syncthreads();
    #pragma unroll
    for (int st = 128; st > 0; st >>= 1) {
        if (tid < st) sbuf[tid] += sbuf[tid + st];
        __syncthreads();
    }
    if (tid == 0) g_bqbk = SCALE * sbuf[0];
    __syncthreads();
}

// one LN-input tile (32 tokens): t in [0,2048)
__device__ void ln_tile(int t, char* smraw, int tid,
                        const float* __restrict__ x,
                        const float* __restrict__ lg,
                        const float* __restrict__ lb) {
    float* sm = (float*)smraw;        // 256*33
    float* ps = sm + 256 * 33;
    float* pq = ps + 256;
    float* mu = pq + 256;
    float* rs = mu + 32;
    int b = t >> 7;
    int tile = t & 127;
    int n0 = tile * 32;
    __syncthreads();

    const float* xb = x + ((size_t)b * CC) * HWN + n0;
    #pragma unroll 8
    for (int it = 0; it < 32; it++) {
        int idx = it * 256 + tid;
        int n = idx & 31, c = idx >> 5;
        sm[c * 33 + n] = xb[(size_t)c * HWN + n];
    }
    __syncthreads();

    int p = tid >> 5, tn = tid & 31;
    float s = 0.f, sq = 0.f;
    #pragma unroll 8
    for (int cc = 0; cc < 32; cc++) {
        float v = sm[(p * 32 + cc) * 33 + tn];
        s += v; sq += v * v;
    }
    ps[p * 32 + tn] = s; pq[p * 32 + tn] = sq;
    __syncthreads();
    if (tid < 32) {
        float S = 0.f, Q = 0.f;
        #pragma unroll
        for (int i = 0; i < 8; i++) { S += ps[i * 32 + tid]; Q += pq[i * 32 + tid]; }
        float m = S * (1.0f / 256.0f);
        float var = Q * (1.0f / 256.0f) - m * m;
        mu[tid] = m;
        rs[tid] = rsqrtf(var + LN_EPS);
    }
    __syncthreads();

    float gc = lg[tid], bc = lb[tid];
    __half* out = g_xnl + ((size_t)(b * HWN + n0)) * CC;
    #pragma unroll 8
    for (int it = 0; it < 32; it++) {
        float v = sm[tid * 33 + it];
        out[(size_t)it * CC + tid] = __float2half_rn((v - mu[it]) * rs[it] * gc + bc);
    }
}

// ---------------- attn tile: 128 tokens via HMMA ----------------
__device__ __forceinline__ void attn_tile(int t, char* smraw, int tid) {
    __half*   sxh  = (__half*)  (smraw + OFF_SX);
    uint2*    bt1  = (uint2*)   (smraw + OFF_BT1);
    uint2*    bt2  = (uint2*)   (smraw + OFF_BT2);
    unsigned* sau  = (unsigned*)(smraw + OFF_SA);
    __half*   sah  = (__half*)  (smraw + OFF_SA);
    float*    sqb  = (float*)   (smraw + OFF_QB);
    float*    sred = (float*)   (smraw + OFF_SRED);

    int b = t >> 5, tile = t & 31;
    int n0 = tile * 128;
    int lane = tid & 31, w = tid >> 5;

    // stage x tile
    const uint4* gx = (const uint4*)(g_xnl + ((size_t)(b * HWN + n0)) * CC);
    #pragma unroll
    for (int it = 0; it < 16; it++) {
        int idx = it * 256 + tid;
        int n = idx >> 5, c8 = idx & 31;
        *(uint4*)(sxh + n * XH + c8 * 8) = gx[idx];
    }
    // bt1: B fragments of qt (fp16), 16 k-steps
    {
        int n = lane >> 2;
        const float* qrow = g_qt + (b * KK + (n & 3)) * CC;
        #pragma unroll
        for (int rep = 0; rep < 2; rep++) {
            int kk = (tid >> 5) + rep * 8;
            int kb = kk * 16 + (lane & 3) * 2;
            unsigned w0 = 0, w1 = 0;
            if (n < 4) {
                w0 = packh2f(qrow[kb], qrow[kb + 1]);
                w1 = packh2f(qrow[kb + 8], qrow[kb + 9]);
            }
            bt1[kk * 32 + lane] = make_uint2(w0, w1);
        }
    }
    if (tid < 4) sqb[tid] = g_qb[b * KK + tid];
    __syncthreads();

    // phase 1: logits, warp w -> tokens [w*16, w*16+16)
    float d[4] = {0.f, 0.f, 0.f, 0.f};
    {
        int mrow = ((lane & 8) ? 8 : 0) + (lane & 7);
        int koff = (lane & 16) ? 8 : 0;
        const __half* abase = sxh + (w * 16 + mrow) * XH + koff;
        #pragma unroll
        for (int kk = 0; kk < 16; kk++) {
            unsigned a0, a1, a2, a3;
            ldm4(a0, a1, a2, a3, abase + kk * 16);
            uint2 bv = bt1[kk * 32 + lane];
            mma16816(d, a0, a1, a2, a3, bv.x, bv.y);
        }
    }
    // softmax: lanes with (lane&3)==0 handle tokens w*16+quad and +8
    {
        float o0 = __shfl_xor_sync(0xffffffffu, d[0], 1);
        float o1 = __shfl_xor_sync(0xffffffffu, d[1], 1);
        float o2 = __shfl_xor_sync(0xffffffffu, d[2], 1);
        float o3 = __shfl_xor_sync(0xffffffffu, d[3], 1);
        float s0 = 0.f, s1 = 0.f, s2 = 0.f, s3 = 0.f;
        if ((lane & 3) == 0) {
            int T0 = w * 16 + (lane >> 2), T1 = T0 + 8;
            float l0 = d[0] + sqb[0], l1 = d[1] + sqb[1];
            float l2 = o0 + sqb[2],   l3 = o1 + sqb[3];
            float mx = fmaxf(fmaxf(l0, l1), fmaxf(l2, l3));
            float e0 = __expf(l0 - mx), e1 = __expf(l1 - mx);
            float e2 = __expf(l2 - mx), e3 = __expf(l3 - mx);
            float inv = __fdividef(1.0f, e0 + e1 + e2 + e3);
            float a0 = e0 * inv, a1 = e1 * inv, a2 = e2 * inv, a3 = e3 * inv;
            sau[T0 * 2]     = packh2f(a0, a1);
            sau[T0 * 2 + 1] = packh2f(a2, a3);
            s0 = a0; s1 = a1; s2 = a2; s3 = a3;
            l0 = d[2] + sqb[0]; l1 = d[3] + sqb[1];
            l2 = o2 + sqb[2];   l3 = o3 + sqb[3];
            mx = fmaxf(fmaxf(l0, l1), fmaxf(l2, l3));
            e0 = __expf(l0 - mx); e1 = __expf(l1 - mx);
            e2 = __expf(l2 - mx); e3 = __expf(l3 - mx);
            inv = __fdividef(1.0f, e0 + e1 + e2 + e3);
            a0 = e0 * inv; a1 = e1 * inv; a2 = e2 * inv; a3 = e3 * inv;
            sau[T1 * 2]     = packh2f(a0, a1);
            sau[T1 * 2 + 1] = packh2f(a2, a3);
            s0 += a0; s1 += a1; s2 += a2; s3 += a3;
        }
        #pragma unroll
        for (int off = 4; off < 32; off <<= 1) {
            s0 += __shfl_xor_sync(0xffffffffu, s0, off);
            s1 += __shfl_xor_sync(0xffffffffu, s1, off);
            s2 += __shfl_xor_sync(0xffffffffu, s2, off);
            s3 += __shfl_xor_sync(0xffffffffu, s3, off);
        }
        if (lane == 0) {
            sred[w * 4 + 0] = s0; sred[w * 4 + 1] = s1;
            sred[w * 4 + 2] = s2; sred[w * 4 + 3] = s3;
        }
    }
    __syncthreads();
    if (tid < 4) {
        float s = 0.f;
        #pragma unroll
        for (int ww = 0; ww < 8; ww++) s += sred[ww * 4 + tid];
        atomicAdd(&g_S[b * KK + tid], s);
    }
    // bt2: B fragments of softmax weights, 8 k-steps
    {
        int kk = tid >> 5;
        int n = lane >> 2;
        int kb = kk * 16 + (lane & 3) * 2;
        unsigned w0 = 0, w1 = 0;
        if (n < 4) {
            w0 = packh2h(sah[kb * 4 + n],       sah[(kb + 1) * 4 + n]);
            w1 = packh2h(sah[(kb + 8) * 4 + n], sah[(kb + 9) * 4 + n]);
        }
        bt2[kk * 32 + lane] = make_uint2(w0, w1);
    }
    __syncthreads();

    // phase 2: A^T[ch][slot] += x^T . a ; warp w -> ch m-tiles w*2, w*2+1
    {
        int tokoff = ((lane & 16) >> 1) + (lane & 7);
        int choff = (lane & 8) ? 8 : 0;
        float e0[4] = {0.f, 0.f, 0.f, 0.f};
        float e1[4] = {0.f, 0.f, 0.f, 0.f};
        int mt0 = w * 2, mt1 = w * 2 + 1;
        const __half* ab0 = sxh + tokoff * XH + mt0 * 16 + choff;
        const __half* ab1 = sxh + tokoff * XH + mt1 * 16 + choff;
        #pragma unroll
        for (int kk = 0; kk < 8; kk++) {
            unsigned a0, a1, a2, a3;
            uint2 bv = bt2[kk * 32 + lane];
            ldm4t(a0, a1, a2, a3, ab0 + kk * 16 * XH);
            mma16816(e0, a0, a1, a2, a3, bv.x, bv.y);
            ldm4t(a0, a1, a2, a3, ab1 + kk * 16 * XH);
            mma16816(e1, a0, a1, a2, a3, bv.x, bv.y);
        }
        if ((lane & 3) < 2) {
            int slot = (lane & 3) * 2;
            int ch0 = mt0 * 16 + (lane >> 2);
            int ch1 = mt1 * 16 + (lane >> 2);
            float* Ab = g_A + b * KK * CC;
            atomicAdd(&Ab[(slot)     * CC + ch0],     e0[0]);
            atomicAdd(&Ab[(slot + 1) * CC + ch0],     e0[1]);
            atomicAdd(&Ab[(slot)     * CC + ch0 + 8], e0[2]);
            atomicAdd(&Ab[(slot + 1) * CC + ch0 + 8], e0[3]);
            atomicAdd(&Ab[(slot)     * CC + ch1],     e1[0]);
            atomicAdd(&Ab[(slot + 1) * CC + ch1],     e1[1]);
            atomicAdd(&Ab[(slot)     * CC + ch1 + 8], e1[2]);
            atomicAdd(&Ab[(slot + 1) * CC + ch1 + 8], e1[3]);
        }
    }
    __syncthreads();
}

// ---------------- qt stage: 256 blocks = 16 rg x 16 os ----------------
__device__ __forceinline__ void qt_stage(char* smraw, int bid, int tid,
                                         const float* lsg, const float* lsb,
                                         int zeroAS) {
    float* uin  = (float*)(smraw + U_OFF_IN);
    float* slab = (float*)(smraw + U_OFF_SLAB);
    float* red  = (float*)(smraw + U_OFF_RED);
    int rg = bid >> 4, os = bid & 15;

    #pragma unroll
    for (int i = 0; i < 4; i++) {
        int idx = i * 256 + tid; int r = idx >> 8, c = idx & 255;
        uin[r * 256 + c] = g_slots[(rg * 4 + r) * 256 + c];
    }
    #pragma unroll
    for (int i = 0; i < 16; i++) {
        int idx = i * 256 + tid; int j = idx >> 8, c = idx & 255;
        slab[j * 260 + c] = g_Wqk[(size_t)(os * 16 + j) * 256 + c];
    }
    __syncthreads();
    ln_apply4(uin, red, lsg, lsb, tid);

    if (os == 0) {
        int r = tid >> 6, t = tid & 63;
        float4 v = ((const float4*)(uin + r * 256))[t];
        float4 w = ((const float4*)g_wqbk)[t];
        float s = v.x * w.x + v.y * w.y + v.z * w.z + v.w * w.w;
        #pragma unroll
        for (int off = 16; off; off >>= 1) s += __shfl_xor_sync(0xffffffffu, s, off);
        if ((tid & 31) == 0) red[(tid >> 5) * 2] = s;
        __syncthreads();
        if (tid < 4) g_qb[rg * 4 + tid] = red[tid * 4] + red[tid * 4 + 2] + g_bqbk;
    }

    int r = tid >> 6, j = (tid >> 2) & 15, cq = tid & 3;
    float acc = 0.f;
    #pragma unroll 8
    for (int ci = 0; ci < 64; ci++) {
        int c = cq + ci * 4;
        acc += uin[r * 256 + c] * slab[j * 260 + c];
    }
    acc += __shfl_xor_sync(0xffffffffu, acc, 1);
    acc += __shfl_xor_sync(0xffffffffu, acc, 2);
    if (cq == 0) {
        int cc = os * 16 + j, row = rg * 4 + r;
        g_qt[row * 256 + cc] = acc + g_qtb[cc];
    }
    if (zeroAS) {
        if (tid < 64) {
            int r2 = tid >> 4, j2 = tid & 15;
            g_A[(rg * 4 + r2) * 256 + os * 16 + j2] = 0.f;
        }
        if (os == 0 && tid < 4) g_S[rg * 4 + tid] = 0.f;
    }
}

// ---------------- THE kernel ----------------
__global__ void __launch_bounds__(256, 2) k_mega(
    const float* __restrict__ x,
    const float* __restrict__ lig,  const float* __restrict__ lib,
    const float* __restrict__ smu,  const float* __restrict__ sls,
    const float* __restrict__ noise,
    const float* __restrict__ lsg,  const float* __restrict__ lsb,
    const float* __restrict__ lmg,  const float* __restrict__ lmb,
    const float* __restrict__ Wq,   const float* __restrict__ bq,
    const float* __restrict__ Wk,   const float* __restrict__ bk,
    const float* __restrict__ Wv,   const float* __restrict__ bv,
    const float* __restrict__ Wu,   const float* __restrict__ bu,
    const float* __restrict__ W1,   const float* __restrict__ b1,
    const float* __restrict__ W2,   const float* __restrict__ b2,
    const float* __restrict__ We1,  const float* __restrict__ be1,
    const float* __restrict__ We2,  const float* __restrict__ be2,
    float* __restrict__ out) {
    extern __shared__ __align__(16) char smraw[];
    float* uin  = (float*)(smraw + U_OFF_IN);
    float* uin2 = (float*)(smraw + U_OFF_IN2);
    float* slab = (float*)(smraw + U_OFF_SLAB);
    float* slab2 = slab + 16 * 260;
    float* red  = (float*)(smraw + U_OFF_RED);
    int bid = blockIdx.x;
    int tid = threadIdx.x;
    int rg = bid >> 4, os = bid & 15;

    // ================= phase 0 =================
    if (bid < 128) {
        prep_unit(bid, smraw, tid, Wq, Wk, bq, Wv, bv, Wu);
    } else if (bid == 128) {
        prep_bias(smraw, tid, Wq, bq, bk);
    } else if (bid < 193) {
        int row = bid - 129;
        float ns = smu[tid] + expf(sls[tid]) * noise[row * 256 + tid];
        g_slots[row * 256 + tid] = ns;
        g_A[row * 256 + tid] = 0.f;
        if (tid == 0) g_S[row] = 0.f;
    }
    if (bid <= 128) {
        #pragma unroll
        for (int i = 0; i < 4; i++) ln_tile(bid * 4 + i, smraw, tid, x, lig, lib);
    } else {
        for (int t = 516 + (bid - 129); t < 2048; t += 127)
            ln_tile(t, smraw, tid, x, lig, lib);
    }
    grid_bar();
    qt_stage(smraw, bid, tid, lsg, lsb, 0);
    grid_bar();

    // ================= 3 iterations =================
    for (int it = 0; it < 3; it++) {
        int last = (it == 2);
        attn_tile(bid, smraw, tid);
        attn_tile(bid + 256, smraw, tid);
        grid_bar();

        // ---- S1: spre ----
        {
            #pragma unroll
            for (int i = 0; i < 4; i++) {
                int idx = i * 256 + tid; int r = idx >> 8, c = idx & 255;
                int row = rg * 4 + r;
                uin[r * 256 + c] = g_slots[row * 256 + c];
                float Sv = g_S[row];
                uin2[r * 256 + c] = g_A[row * 256 + c] * (1.0f / (Sv + EPS_W));
            }
            #pragma unroll
            for (int i = 0; i < 16; i++) {
                int idx = i * 256 + tid; int j = idx >> 8, c = idx & 255;
                slab [j * 260 + c] = Wu[(size_t)(os * 16 + j) * 512 + c];
                slab2[j * 260 + c] = g_Wvu[(size_t)(os * 16 + j) * 256 + c];
            }
            __syncthreads();
            int r = tid >> 6, j = (tid >> 2) & 15, cq = tid & 3;
            float acc = 0.f;
            #pragma unroll 8
            for (int ci = 0; ci < 64; ci++) {
                int c = cq + ci * 4;
                acc += uin[r * 256 + c] * slab[j * 260 + c]
                     + uin2[r * 256 + c] * slab2[j * 260 + c];
            }
            acc += __shfl_xor_sync(0xffffffffu, acc, 1);
            acc += __shfl_xor_sync(0xffffffffu, acc, 2);
            if (cq == 0) {
                int d = os * 16 + j, row = rg * 4 + r;
                float Sv = g_S[row];
                float beta = Sv / (Sv + EPS_W);
                g_spre[row * 256 + d] = acc + bu[d] + uin[r * 256 + d]
                                      + beta * g_bvu[d];
            }
        }
        grid_bar();

        // ---- S2: h = gelu(LN_mlp(spre) @ W1^T + b1) ----
        {
            #pragma unroll
            for (int i = 0; i < 4; i++) {
                int idx = i * 256 + tid; int r = idx >> 8, c = idx & 255;
                uin[r * 256 + c] = g_spre[(rg * 4 + r) * 256 + c];
            }
            #pragma unroll
            for (int i = 0; i < 32; i++) {
                int idx = i * 256 + tid; int j = idx >> 8, c = idx & 255;
                slab[j * 258 + c] = W1[(size_t)(os * 32 + j) * 256 + c];
            }
            __syncthreads();
            ln_apply4(uin, red, lmg, lmb, tid);
            int r = tid >> 6, j = (tid >> 1) & 31, ch = tid & 1;
            float acc = 0.f;
            #pragma unroll 8
            for (int ci = 0; ci < 128; ci++) {
                int c = ch + ci * 2;
                acc += uin[r * 256 + c] * slab[j * 258 + c];
            }
            acc += __shfl_xor_sync(0xffffffffu, acc, 1);
            if (ch == 0) {
                int jj = os * 32 + j, row = rg * 4 + r;
                g_h[row * 512 + jj] = gelu_f(acc + b1[jj]);
            }
        }
        grid_bar();

        // ---- S3: slots = spre + h @ W2^T + b2 ----
        {
            #pragma unroll
            for (int i = 0; i < 8; i++) {
                int idx = i * 256 + tid; int r = idx >> 9, c = idx & 511;
                uin[r * 512 + c] = g_h[(rg * 4 + r) * 512 + c];
            }
            #pragma unroll
            for (int i = 0; i < 32; i++) {
                int idx = i * 256 + tid; int j = idx >> 9, c = idx & 511;
                slab[j * 516 + c] = W2[(size_t)(os * 16 + j) * 512 + c];
            }
            __syncthreads();
            int r = tid >> 6, j = (tid >> 2) & 15, cq = tid & 3;
            float acc = 0.f;
            #pragma unroll 8
            for (int ci = 0; ci < 128; ci++) {
                int c = cq + ci * 4;
                acc += uin[r * 512 + c] * slab[j * 516 + c];
            }
            acc += __shfl_xor_sync(0xffffffffu, acc, 1);
            acc += __shfl_xor_sync(0xffffffffu, acc, 2);
            if (cq == 0) {
                int d = os * 16 + j, row = rg * 4 + r;
                float val = acc + b2[d] + g_spre[row * 256 + d];
                g_slots[row * 256 + d] = val;
                if (last) out[row * 256 + d] = val;
            }
        }
        grid_bar();

        if (!last) {
            qt_stage(smraw, bid, tid, lsg, lsb, 1);
            grid_bar();
        } else {
            // ---- head: e = gelu(We1 @ slots + be1) -> g_qt reuse ----
            #pragma unroll
            for (int i = 0; i < 4; i++) {
                int idx = i * 256 + tid; int r = idx >> 8, c = idx & 255;
                uin[r * 256 + c] = g_slots[(rg * 4 + r) * 256 + c];
            }
            #pragma unroll
            for (int i = 0; i < 8; i++) {
                int idx = i * 256 + tid; int j = idx >> 8, c = idx & 255;
                slab[j * 264 + c] = We1[(size_t)(os * 8 + j) * 256 + c];
            }
            __syncthreads();
            int r = tid >> 6, j = (tid >> 3) & 7, c8 = tid & 7;
            float acc = 0.f;
            #pragma unroll 8
            for (int ci = 0; ci < 32; ci++) {
                int c = c8 + ci * 8;
                acc += uin[r * 256 + c] * slab[j * 264 + c];
            }
            acc += __shfl_xor_sync(0xffffffffu, acc, 1);
            acc += __shfl_xor_sync(0xffffffffu, acc, 2);
            acc += __shfl_xor_sync(0xffffffffu, acc, 4);
            if (c8 == 0) {
                int jj = os * 8 + j, row = rg * 4 + r;
                g_qt[row * 256 + jj] = gelu_f(acc + be1[jj]);
            }
            grid_bar();
            if (bid == 0) {
                int row = tid >> 2, p = tid & 3;
                float a2 = 0.f;
                #pragma unroll 8
                for (int k2 = 0; k2 < 32; k2++) {
                    int j2 = p + k2 * 4;
                    a2 += g_qt[row * 256 + j2] * We2[j2];
                }
                a2 += __shfl_xor_sync(0xffffffffu, a2, 1);
                a2 += __shfl_xor_sync(0xffffffffu, a2, 2);
                if (p == 0)
                    out[BB * KK * CC + row] = 1.0f / (1.0f + expf(-(a2 + be2[0])));
            }
        }
    }
}

// ---------------- host ----------------
extern "C" void kernel_launch(void* const* d_in, const int* in_sizes, int n_in,
                              void* d_out, int out_size) {
    const float* x        = (const float*)d_in[0];
    const float* noise    = (const float*)d_in[1];
    const float* slot_mu  = (const float*)d_in[2];
    const float* slot_ls  = (const float*)d_in[3];
    const float* ln_in_g  = (const float*)d_in[4];
    const float* ln_in_b  = (const float*)d_in[5];
    const float* ln_sl_g  = (const float*)d_in[6];
    const float* ln_sl_b  = (const float*)d_in[7];
    const float* ln_mlp_g = (const float*)d_in[8];
    const float* ln_mlp_b = (const float*)d_in[9];
    const float* Wq = (const float*)d_in[10];
    const float* bq = (const float*)d_in[11];
    const float* Wk = (const float*)d_in[12];
    const float* bk = (const float*)d_in[13];
    const float* Wv = (const float*)d_in[14];
    const float* bv = (const float*)d_in[15];
    const float* Wu = (const float*)d_in[16];
    const float* bu = (const float*)d_in[17];
    const float* W1 = (const float*)d_in[18];
    const float* b1 = (const float*)d_in[19];
    const float* W2 = (const float*)d_in[20];
    const float* b2 = (const float*)d_in[21];
    const float* We1 = (const float*)d_in[22];
    const float* be1 = (const float*)d_in[23];
    const float* We2 = (const float*)d_in[24];
    const float* be2 = (const float*)d_in[25];
    float* out = (float*)d_out;

    static int attr_set = 0;
    if (!attr_set) {
        cudaFuncSetAttribute(k_mega, cudaFuncAttributeMaxDynamicSharedMemorySize,
                             SMEM_DYN);
        attr_set = 1;
    }

    k_mega<<<NBLK, 256, SMEM_DYN>>>(x, ln_in_g, ln_in_b,
                                    slot_mu, slot_ls, noise,
                                    ln_sl_g, ln_sl_b, ln_mlp_g, ln_mlp_b,
                                    Wq, bq, Wk, bk, Wv, bv, Wu, bu,
                                    W1, b1, W2, b2,
                                    We1, be1, We2, be2, out);
}